// round 15
// baseline (speedup 1.0000x reference)
#include <cuda_runtime.h>
#include <cuda_fp16.h>
#include <cstdint>
#include <cstddef>

// ---------------- problem constants ----------------
static constexpr int T_TOK = 8192;
static constexpr int HID   = 4096;
static constexpr int NOUT  = 6144;   // Q(4096) + K(1024) + V(1024)
static constexpr int QS    = 4096;
static constexpr int KVS   = 1024;
static constexpr int RANK  = 16;
static constexpr int SEXT  = 128;    // per-section ext: 8 slots * 16 ranks
static constexpr int KTOT2 = HID + SEXT;  // 4224 (GEMM2 K)
static constexpr int NT1   = 192;    // GEMM1 tile count (3 N x 64 M)

// ---------------- scratch (static device memory; no allocation) ----------------
__device__ __align__(1024) __half g_xh[(size_t)T_TOK * HID];    // 67 MB
__device__ __align__(1024) __half g_wh[(size_t)NOUT * KTOT2];   // 51.9 MB
__device__ __align__(1024) __half g_ah[(size_t)3 * SEXT * HID]; //  3.1 MB (PERMUTED rows)
__device__ __align__(1024) __half g_xe[3][(size_t)T_TOK * SEXT];//  6.3 MB
__device__ unsigned g_done = 0;      // GEMM1-tile completion counter (reset by prep)

// ---------------- PTX helpers (base-target only: sm_80+ features) ----------------
__device__ __forceinline__ uint32_t smem_u32(const void* p) {
    uint32_t a;
    asm("{ .reg .u64 t; cvta.to.shared.u64 t, %1; cvt.u32.u64 %0, t; }" : "=r"(a) : "l"(p));
    return a;
}

__device__ __forceinline__ void cp_async16(uint32_t dst, const void* src) {
    asm volatile("cp.async.cg.shared.global [%0], [%1], 16;\n" :: "r"(dst), "l"(src) : "memory");
}

#define CP_COMMIT()  asm volatile("cp.async.commit_group;\n" ::: "memory")
#define CP_WAIT(n)   asm volatile("cp.async.wait_group %0;\n" :: "n"(n) : "memory")

__device__ __forceinline__ uint32_t sw128(uint32_t off) {
    return off ^ ((off >> 3) & 0x70);
}

__device__ __forceinline__ void ldmatrix_x4(uint32_t* r, uint32_t addr) {
    asm volatile("ldmatrix.sync.aligned.m8n8.x4.shared.b16 {%0,%1,%2,%3}, [%4];"
                 : "=r"(r[0]), "=r"(r[1]), "=r"(r[2]), "=r"(r[3]) : "r"(addr));
}

__device__ __forceinline__ void mma16816(float* c, const uint32_t* a, uint32_t b0, uint32_t b1) {
    asm volatile("mma.sync.aligned.m16n8k16.row.col.f32.f16.f16.f32 "
                 "{%0,%1,%2,%3}, {%4,%5,%6,%7}, {%8,%9}, {%0,%1,%2,%3};"
                 : "+f"(c[0]), "+f"(c[1]), "+f"(c[2]), "+f"(c[3])
                 : "r"(a[0]), "r"(a[1]), "r"(a[2]), "r"(a[3]), "r"(b0), "r"(b1));
}

// ---------------- conversion helpers ----------------
__device__ __forceinline__ uint4 pack8(float4 a, float4 b) {
    __half2 h0 = __floats2half2_rn(a.x, a.y);
    __half2 h1 = __floats2half2_rn(a.z, a.w);
    __half2 h2 = __floats2half2_rn(b.x, b.y);
    __half2 h3 = __floats2half2_rn(b.z, b.w);
    uint4 u;
    u.x = *reinterpret_cast<uint32_t*>(&h0);
    u.y = *reinterpret_cast<uint32_t*>(&h1);
    u.z = *reinterpret_cast<uint32_t*>(&h2);
    u.w = *reinterpret_cast<uint32_t*>(&h3);
    return u;
}

__device__ __forceinline__ void cvt8(const float* __restrict__ src, __half* __restrict__ dst,
                                     int idx, int dld) {
    const int cols8 = HID / 8;  // 512
    int r = idx / cols8, c = idx % cols8;
    const float4* p = reinterpret_cast<const float4*>(src + (size_t)r * HID + (size_t)c * 8);
    float4 f0 = p[0], f1 = p[1];
    *reinterpret_cast<uint4*>(dst + (size_t)r * dld + (size_t)c * 8) = pack8(f0, f1);
}

// full prep: x->xh, lora_A->ah (permuted), W->wh (ld 4224), W-ext fill.
// Also resets the g_done counter for the fused GEMM launch (each graph replay).
__global__ void __launch_bounds__(256)
prep_kernel(const float* __restrict__ x, const float* __restrict__ lA,
            const float* __restrict__ W,
            const float* __restrict__ bq, const float* __restrict__ bk,
            const float* __restrict__ bv,
            __half* __restrict__ xh, __half* __restrict__ ah, __half* __restrict__ wh) {
    if (blockIdx.x == 0 && threadIdx.x == 0) g_done = 0;
    int idx = blockIdx.x * blockDim.x + threadIdx.x;
    const int n1 = T_TOK * 512;       // x -> xh (fp16, ld 4096)
    const int n2 = 3 * SEXT * 512;    // lora_A -> ah (fp16, PERMUTED rows, ld 4096)
    const int n3 = NOUT * 512;        // W -> wh (fp16, ld 4224)
    const int n4 = NOUT * SEXT;       // W extension columns (one section per row)
    if (idx < n1) { cvt8(x, xh, idx, HID); return; }
    idx -= n1;
    if (idx < n2) {
        // lora_A natural row = s*48 + i*16 + r; permute to drow = i*128 + s*16 + r
        int row = idx >> 9, c8 = idx & 511;
        int s = row / 48, rem = row % 48;
        int i = rem >> 4, r = rem & 15;
        int drow = i * SEXT + s * RANK + r;
        const float4* p = reinterpret_cast<const float4*>(lA + (size_t)row * HID + (size_t)c8 * 8);
        float4 f0 = p[0], f1 = p[1];
        *reinterpret_cast<uint4*>(ah + (size_t)drow * HID + (size_t)c8 * 8) = pack8(f0, f1);
        return;
    }
    idx -= n2;
    if (idx < n3) { cvt8(W, wh, idx, KTOT2); return; }
    idx -= n3;
    if (idx < n4) {
        int n = idx / SEXT, j = idx % SEXT;   // j = s*16 + r
        int s = j >> 4, r = j & 15;
        float v;
        if (n < QS)            v = bq[((size_t)s * QS + n) * RANK + r];
        else if (n < QS + KVS) v = bk[((size_t)s * KVS + (n - QS)) * RANK + r];
        else                   v = bv[((size_t)s * KVS + (n - QS - KVS)) * RANK + r];
        wh[(size_t)n * KTOT2 + HID + j] = __float2half(v);
    }
}

// ---------------- GEMM body (templated on GEMM1 vs GEMM2) ----------------
// R14 base (929us @ tensor 80.2%) + fragment-latency pipelining:
//  - bfr double-buffered: bfr[ks+1] LDSMs issue BEFORE the MMAs of ks (no WAR,
//    29-cyc LDSM latency covered by 32 HMMA issues).
//  - afr interleaved-reload: afr[mi](ks+1) reloads right after mi's 8 MMAs issue
//    (single buffer, zero extra registers, >=96 cyc of cover).
// Cross-chunk preload stays RACE-FREE: next chunk's ks0 fragments load only
// AFTER CP_WAIT(1)+__syncthreads (pre-barrier loads are a data race; see R9).
// G1: B=ah (ld HID), nct=64, LoRA route/scale epilogue -> ext bufs, then
//     threadfence + atomicAdd(g_done).
// G2: B=wh (ld 4224), nct=66; chunks >= 64 read ext bufs -> loader spin-waits
//     g_done==NT1 before issuing them. Deadlock-free: all NT1 G1 tiles have the
//     lowest block ids -> co-resident in wave 1 (296 slots), and never wait.
template<bool G1>
__device__ __forceinline__ void gemm_body(
    int tv, const __half* __restrict__ A, const __half* __restrict__ Bp,
    float* __restrict__ C, const int* __restrict__ t2s, const float* __restrict__ sc,
    __half* __restrict__ e0, __half* __restrict__ e1, __half* __restrict__ e2,
    char* smem) {
    constexpr int BM = 128, BN = 128, BK = 64;
    constexpr int THREADS = 128;
    constexpr int STAGE_A = BM * BK * 2;          // 16 KB
    constexpr int STAGE_B = BN * BK * 2;          // 16 KB
    constexpr int STAGE   = STAGE_A + STAGE_B;    // 32 KB
    constexpr int NSTAGE  = 3;
    constexpr int MT  = 4;                        // 16-row m-tiles per warp (64 rows)
    constexpr int NTL = 8;                        // 8-col n-tiles per warp (64 cols)
    constexpr int NPAIR = 4;                      // ldmatrix.x4 loads for B per k-step
    constexpr int ntn    = G1 ? 3 : 48;
    constexpr int ldb    = G1 ? HID : KTOT2;
    constexpr int nctot  = G1 ? 64 : 66;
    constexpr int NCBASE = 64;                    // chunks < 64 come from A (xh)

    const int tid  = threadIdx.x;
    const int wid  = tid >> 5, lane = tid & 31;
    const int wm   = wid & 1, wn = wid >> 1;      // 2 x 2 warp grid
    const int m0   = (tv / ntn) * BM;
    const int n0   = (tv % ntn) * BN;
    const uint32_t s_base = smem_u32(smem);

    const __half* AE = nullptr;                   // G2 ext tail source
    if constexpr (!G1) AE = (n0 < QS) ? e0 : (n0 < QS + KVS) ? e1 : e2;

    const int lr   = lane & 7;   // row within 8x8 ldmatrix
    const int lsub = lane >> 3;  // which 8x8 matrix this lane's address feeds
    const int g    = lane >> 2;  // mma group row
    const int t    = lane & 3;   // mma thread-in-group

    bool flag_seen = G1;         // G1 tiles never wait

    auto load_stage = [&](int stage, int c) {
        const uint32_t sa = s_base + stage * STAGE;
        const __half* srcA; size_t ldA;
        if constexpr (G1) {
            srcA = A + (size_t)m0 * HID + (size_t)c * BK; ldA = (size_t)HID;
        } else {
            if (c < NCBASE) {
                srcA = A + (size_t)m0 * HID + (size_t)c * BK; ldA = (size_t)HID;
            } else {
                if (!flag_seen) {
                    while (*((volatile unsigned*)&g_done) < (unsigned)NT1) { }
                    __threadfence();
                    flag_seen = true;
                }
                srcA = AE + (size_t)m0 * SEXT + (size_t)(c - NCBASE) * BK; ldA = SEXT;
            }
        }
        const __half* srcB = Bp + (size_t)n0 * ldb + (size_t)c * BK;
        #pragma unroll
        for (int i = 0; i < BM * 8 / THREADS; i++) {
            int id = tid + i * THREADS; int row = id >> 3, cc = id & 7;
            uint32_t off = (uint32_t)(row * 128 + cc * 16);
            cp_async16(sa + sw128(off), (const char*)srcA + row * ldA * 2 + cc * 16);
        }
        #pragma unroll
        for (int i = 0; i < BN * 8 / THREADS; i++) {
            int id = tid + i * THREADS; int row = id >> 3, cc = id & 7;
            uint32_t off = (uint32_t)(row * 128 + cc * 16);
            cp_async16(sa + STAGE_A + sw128(off), (const char*)srcB + (size_t)row * ldb * 2 + cc * 16);
        }
        CP_COMMIT();
    };

    #pragma unroll
    for (int s = 0; s < NSTAGE; s++) load_stage(s, s);   // prologue: 3 stages in flight

    float acc[MT][NTL][4];
    #pragma unroll
    for (int mi = 0; mi < MT; mi++)
        #pragma unroll
        for (int ni = 0; ni < NTL; ni++)
            #pragma unroll
            for (int q = 0; q < 4; q++) acc[mi][ni][q] = 0.f;

    uint32_t afr[MT][4], bfr[2][NPAIR][4];

    auto a_addr = [&](uint32_t sa, int ks, int mi) -> uint32_t {
        int row  = wm * 64 + mi * 16 + (lsub & 1) * 8 + lr;
        int colh = ks * 16 + (lsub >> 1) * 8;
        uint32_t off = (uint32_t)(row * 128 + colh * 2);
        return sa + sw128(off);
    };
    auto frag_load_a = [&](uint32_t sa, int ks) {
        #pragma unroll
        for (int mi = 0; mi < MT; mi++) ldmatrix_x4(afr[mi], a_addr(sa, ks, mi));
    };
    auto frag_load_b = [&](int buf, uint32_t sb, int ks) {
        #pragma unroll
        for (int pi = 0; pi < NPAIR; pi++) {
            int row  = wn * 64 + pi * 16 + (lsub >> 1) * 8 + lr;
            int colh = ks * 16 + (lsub & 1) * 8;
            uint32_t off = (uint32_t)(row * 128 + colh * 2);
            ldmatrix_x4(bfr[buf][pi], sb + sw128(off));
        }
    };

    // wait for chunk 0 (3 groups outstanding -> <=2 leaves chunk 0 complete)
    CP_WAIT(2);
    __syncthreads();
    frag_load_a(s_base, 0);
    frag_load_b(0, s_base + STAGE_A, 0);

    int stage_c = 0;
    for (int c = 0; c < nctot; c++) {
        const uint32_t sa = s_base + stage_c * STAGE;
        const uint32_t sb = sa + STAGE_A;
        const int stage_n = (stage_c + 1 == NSTAGE) ? 0 : stage_c + 1;
        const uint32_t sa_n = s_base + stage_n * STAGE;

        #pragma unroll
        for (int ks = 0; ks < 4; ks++) {
            const int cur = ks & 1;
            // B frags for ks+1: independent buffer -> issue BEFORE the MMAs
            if (ks < 3) frag_load_b(cur ^ 1, sb, ks + 1);
            #pragma unroll
            for (int mi = 0; mi < MT; mi++) {
                #pragma unroll
                for (int ni = 0; ni < NTL; ni++)
                    mma16816(acc[mi][ni], afr[mi],
                             bfr[cur][ni >> 1][(ni & 1) * 2 + 0],
                             bfr[cur][ni >> 1][(ni & 1) * 2 + 1]);
                // afr[mi] dead after its 8 MMAs issue -> reload for ks+1 now
                if (ks < 3) ldmatrix_x4(afr[mi], a_addr(sa, ks + 1, mi));
            }
        }

        // complete chunk c+1 in THIS thread, then barrier: all threads' waits
        // have executed -> chunk c+1 smem writes published, stage (c%3) reads done.
        CP_WAIT(1);
        __syncthreads();
        if (c + 1 < nctot) {                       // safe: post-barrier
            frag_load_a(sa_n, 0);
            frag_load_b(0, sa_n + STAGE_A, 0);
        }
        if (c + NSTAGE < nctot) load_stage(stage_c, c + NSTAGE);
        else CP_COMMIT();                          // keep group count uniform
        stage_c = stage_n;
    }

    if constexpr (G1) {
        // LoRA down-proj epilogue: route + scale + fp16 store into per-target ext
        // bufs. Column j in [0,384) is per-target order (prep permuted lora_A):
        // target = j>>7, rem = j&127 = slot*16 + rank.
        #pragma unroll
        for (int mi = 0; mi < MT; mi++) {
            int r0 = m0 + wm * 64 + mi * 16 + g;
            int slot0 = t2s[r0], slot1 = t2s[r0 + 8];
            float s0 = sc[slot0], s1 = sc[slot1];
            #pragma unroll
            for (int ni = 0; ni < NTL; ni++) {
                int j = n0 + wn * 64 + ni * 8 + 2 * t;
                int it = j >> 7, rem = j & 127;
                int s = rem >> 4;
                __half* ebuf = (it == 0) ? e0 : (it == 1) ? e1 : e2;
                __half2 h0 = (s == slot0)
                    ? __floats2half2_rn(s0 * acc[mi][ni][0], s0 * acc[mi][ni][1])
                    : __floats2half2_rn(0.f, 0.f);
                __half2 h1 = (s == slot1)
                    ? __floats2half2_rn(s1 * acc[mi][ni][2], s1 * acc[mi][ni][3])
                    : __floats2half2_rn(0.f, 0.f);
                *reinterpret_cast<__half2*>(ebuf + (size_t)r0 * SEXT + rem)       = h0;
                *reinterpret_cast<__half2*>(ebuf + (size_t)(r0 + 8) * SEXT + rem) = h1;
            }
        }
        // release: xe visible, then count this tile done
        __threadfence();
        __syncthreads();
        if (tid == 0) atomicAdd(&g_done, 1u);
    } else {
        // fp32 epilogue: streaming stores (write-once output; don't evict the
        // L2-resident W stream that every wave re-reads)
        #pragma unroll
        for (int mi = 0; mi < MT; mi++) {
            int r0 = m0 + wm * 64 + mi * 16 + g;
            #pragma unroll
            for (int ni = 0; ni < NTL; ni++) {
                int col = n0 + wn * 64 + ni * 8 + 2 * t;
                float2 v0 = make_float2(acc[mi][ni][0], acc[mi][ni][1]);
                float2 v1 = make_float2(acc[mi][ni][2], acc[mi][ni][3]);
                __stcs(reinterpret_cast<float2*>(C + (size_t)r0 * NOUT + col), v0);
                __stcs(reinterpret_cast<float2*>(C + (size_t)(r0 + 8) * NOUT + col), v1);
            }
        }
    }
}

// ---------------- fused GEMM1+GEMM2 (single launch) ----------------
__global__ void __launch_bounds__(128, 2)
hgemm_fused_kernel(const __half* __restrict__ A, const __half* __restrict__ B1,
                   const __half* __restrict__ B2, float* __restrict__ C,
                   const int* __restrict__ t2s, const float* __restrict__ sc,
                   __half* __restrict__ e0, __half* __restrict__ e1,
                   __half* __restrict__ e2) {
    extern __shared__ char smem[];
    const int tau = (int)blockIdx.x;
    if (tau < NT1) gemm_body<true >(tau,       A, B1, C, t2s, sc, e0, e1, e2, smem);
    else           gemm_body<false>(tau - NT1, A, B2, C, t2s, sc, e0, e1, e2, smem);
}

// ---------------- launch ----------------
extern "C" void kernel_launch(void* const* d_in, const int* in_sizes, int n_in,
                              void* d_out, int out_size) {
    (void)in_sizes; (void)n_in; (void)out_size;
    const float* x   = (const float*)d_in[0];
    const float* W   = (const float*)d_in[1];
    const float* lA  = (const float*)d_in[2];
    const float* bq  = (const float*)d_in[3];
    const float* bk  = (const float*)d_in[4];
    const float* bv  = (const float*)d_in[5];
    const float* sc  = (const float*)d_in[6];
    const int*   t2s = (const int*)d_in[7];
    float* out = (float*)d_out;

    void *xh_p, *wh_p, *ah_p, *xe_p;
    cudaGetSymbolAddress(&xh_p, g_xh);
    cudaGetSymbolAddress(&wh_p, g_wh);
    cudaGetSymbolAddress(&ah_p, g_ah);
    cudaGetSymbolAddress(&xe_p, g_xe);
    __half* xh = (__half*)xh_p;
    __half* wh = (__half*)wh_p;
    __half* ah = (__half*)ah_p;
    __half* xe0 = (__half*)xe_p;
    __half* xe1 = xe0 + (size_t)T_TOK * SEXT;
    __half* xe2 = xe1 + (size_t)T_TOK * SEXT;

    constexpr int SMEM = 3 * (128 * 64 * 2 + 128 * 64 * 2);  // 98304 (2 CTAs/SM)
    cudaFuncSetAttribute((const void*)hgemm_fused_kernel,
                         cudaFuncAttributeMaxDynamicSharedMemorySize, SMEM);

    // 1) full prep: x->fp16, lora_A->fp16 (permuted), W->fp16 + ext fill;
    //    also resets g_done for this replay. (~44us, at the DRAM roofline.)
    {
        int total = T_TOK * 512 + 3 * SEXT * 512 + NOUT * 512 + NOUT * SEXT;
        prep_kernel<<<(total + 255) / 256, 256>>>(x, lA, W, bq, bk, bv, xh, ah, wh);
    }

    // 2) fused GEMM1 + GEMM2 in one launch:
    //    taus [0,192): a[T,384] = xh @ ah^T with route/scale epilogue -> xe bufs
    //    taus [192, 3264): out = [xh | xe_sec][T,4224] @ W'[6144,4224]^T
    {
        int grid = NT1 + (NOUT / 128) * (T_TOK / 128);   // 192 + 3072
        hgemm_fused_kernel<<<grid, 128, SMEM>>>(
            xh, ah, wh, out, t2s, sc, xe0, xe1, xe2);
    }
}

// round 16
// speedup vs baseline: 1.0058x; 1.0058x over previous
#include <cuda_runtime.h>
#include <cuda_fp16.h>
#include <cstdint>
#include <cstddef>

// ---------------- problem constants ----------------
static constexpr int T_TOK = 8192;
static constexpr int HID   = 4096;
static constexpr int NOUT  = 6144;   // Q(4096) + K(1024) + V(1024)
static constexpr int QS    = 4096;
static constexpr int KVS   = 1024;
static constexpr int RANK  = 16;
static constexpr int SEXT  = 128;    // per-section ext: 8 slots * 16 ranks
static constexpr int KTOT2 = HID + SEXT;  // 4224 (GEMM2 K)
static constexpr int NT1    = 192;   // GEMM1 tile count (3 N x 64 M)
static constexpr int NFULL2 = 3064;  // full 128x128 G2 tiles; 192+3064 = 3256 = 296*11
                                     // (the remaining 8 G2 tiles are split into 16 thin
                                     //  128x64 tiles that pack the final partial wave)

// ---------------- scratch (static device memory; no allocation) ----------------
__device__ __align__(1024) __half g_xh[(size_t)T_TOK * HID];    // 67 MB
__device__ __align__(1024) __half g_wh[(size_t)NOUT * KTOT2];   // 51.9 MB
__device__ __align__(1024) __half g_ah[(size_t)3 * SEXT * HID]; //  3.1 MB (PERMUTED rows)
__device__ __align__(1024) __half g_xe[3][(size_t)T_TOK * SEXT];//  6.3 MB
__device__ unsigned g_done = 0;      // GEMM1-tile completion counter (reset by prep)

// ---------------- PTX helpers (base-target only: sm_80+ features) ----------------
__device__ __forceinline__ uint32_t smem_u32(const void* p) {
    uint32_t a;
    asm("{ .reg .u64 t; cvta.to.shared.u64 t, %1; cvt.u32.u64 %0, t; }" : "=r"(a) : "l"(p));
    return a;
}

__device__ __forceinline__ void cp_async16(uint32_t dst, const void* src) {
    asm volatile("cp.async.cg.shared.global [%0], [%1], 16;\n" :: "r"(dst), "l"(src) : "memory");
}

#define CP_COMMIT()  asm volatile("cp.async.commit_group;\n" ::: "memory")
#define CP_WAIT(n)   asm volatile("cp.async.wait_group %0;\n" :: "n"(n) : "memory")

__device__ __forceinline__ uint32_t sw128(uint32_t off) {
    return off ^ ((off >> 3) & 0x70);
}

__device__ __forceinline__ void ldmatrix_x4(uint32_t* r, uint32_t addr) {
    asm volatile("ldmatrix.sync.aligned.m8n8.x4.shared.b16 {%0,%1,%2,%3}, [%4];"
                 : "=r"(r[0]), "=r"(r[1]), "=r"(r[2]), "=r"(r[3]) : "r"(addr));
}

__device__ __forceinline__ void mma16816(float* c, const uint32_t* a, uint32_t b0, uint32_t b1) {
    asm volatile("mma.sync.aligned.m16n8k16.row.col.f32.f16.f16.f32 "
                 "{%0,%1,%2,%3}, {%4,%5,%6,%7}, {%8,%9}, {%0,%1,%2,%3};"
                 : "+f"(c[0]), "+f"(c[1]), "+f"(c[2]), "+f"(c[3])
                 : "r"(a[0]), "r"(a[1]), "r"(a[2]), "r"(a[3]), "r"(b0), "r"(b1));
}

// ---------------- conversion helpers ----------------
__device__ __forceinline__ uint4 pack8(float4 a, float4 b) {
    __half2 h0 = __floats2half2_rn(a.x, a.y);
    __half2 h1 = __floats2half2_rn(a.z, a.w);
    __half2 h2 = __floats2half2_rn(b.x, b.y);
    __half2 h3 = __floats2half2_rn(b.z, b.w);
    uint4 u;
    u.x = *reinterpret_cast<uint32_t*>(&h0);
    u.y = *reinterpret_cast<uint32_t*>(&h1);
    u.z = *reinterpret_cast<uint32_t*>(&h2);
    u.w = *reinterpret_cast<uint32_t*>(&h3);
    return u;
}

__device__ __forceinline__ void cvt8(const float* __restrict__ src, __half* __restrict__ dst,
                                     int idx, int dld) {
    const int cols8 = HID / 8;  // 512
    int r = idx / cols8, c = idx % cols8;
    const float4* p = reinterpret_cast<const float4*>(src + (size_t)r * HID + (size_t)c * 8);
    float4 f0 = p[0], f1 = p[1];
    *reinterpret_cast<uint4*>(dst + (size_t)r * dld + (size_t)c * 8) = pack8(f0, f1);
}

// full prep: x->xh, lora_A->ah (permuted), W->wh (ld 4224), W-ext fill.
// Also resets the g_done counter for the fused GEMM launch (each graph replay).
__global__ void __launch_bounds__(256)
prep_kernel(const float* __restrict__ x, const float* __restrict__ lA,
            const float* __restrict__ W,
            const float* __restrict__ bq, const float* __restrict__ bk,
            const float* __restrict__ bv,
            __half* __restrict__ xh, __half* __restrict__ ah, __half* __restrict__ wh) {
    if (blockIdx.x == 0 && threadIdx.x == 0) g_done = 0;
    int idx = blockIdx.x * blockDim.x + threadIdx.x;
    const int n1 = T_TOK * 512;       // x -> xh (fp16, ld 4096)
    const int n2 = 3 * SEXT * 512;    // lora_A -> ah (fp16, PERMUTED rows, ld 4096)
    const int n3 = NOUT * 512;        // W -> wh (fp16, ld 4224)
    const int n4 = NOUT * SEXT;       // W extension columns (one section per row)
    if (idx < n1) { cvt8(x, xh, idx, HID); return; }
    idx -= n1;
    if (idx < n2) {
        // lora_A natural row = s*48 + i*16 + r; permute to drow = i*128 + s*16 + r
        int row = idx >> 9, c8 = idx & 511;
        int s = row / 48, rem = row % 48;
        int i = rem >> 4, r = rem & 15;
        int drow = i * SEXT + s * RANK + r;
        const float4* p = reinterpret_cast<const float4*>(lA + (size_t)row * HID + (size_t)c8 * 8);
        float4 f0 = p[0], f1 = p[1];
        *reinterpret_cast<uint4*>(ah + (size_t)drow * HID + (size_t)c8 * 8) = pack8(f0, f1);
        return;
    }
    idx -= n2;
    if (idx < n3) { cvt8(W, wh, idx, KTOT2); return; }
    idx -= n3;
    if (idx < n4) {
        int n = idx / SEXT, j = idx % SEXT;   // j = s*16 + r
        int s = j >> 4, r = j & 15;
        float v;
        if (n < QS)            v = bq[((size_t)s * QS + n) * RANK + r];
        else if (n < QS + KVS) v = bk[((size_t)s * KVS + (n - QS)) * RANK + r];
        else                   v = bv[((size_t)s * KVS + (n - QS - KVS)) * RANK + r];
        wh[(size_t)n * KTOT2 + HID + j] = __float2half(v);
    }
}

// ---------------- GEMM body (R14 inner loop, templated on role + tile width) ----------------
// 128xBN CTA tile, 128 threads (4 warps 2x2, warp tile 64x(BN/2)), 3-stage cp.async
// -> 2 CTAs/SM with decoupled barriers. RACE-FREE cross-chunk fragment pipelining:
// next chunk's ks0 fragments load only AFTER CP_WAIT(1)+__syncthreads (pre-barrier
// loads are a data race; see R9). Single fragment buffers (R15's double-buffer hit
// the 255-reg wall and regressed; do not reintroduce).
// G1: B=ah (ld HID), nct=64, LoRA route/scale epilogue -> ext bufs, then
//     threadfence + atomicAdd(g_done).
// G2: B=wh (ld 4224), nct=66; chunks >= 64 read ext bufs -> loader spin-waits
//     g_done==NT1 before issuing them. Deadlock-free: all NT1 G1 tiles have the
//     lowest block ids -> co-resident in wave 1 (296 slots), and never wait.
template<bool G1, int BN>
__device__ __forceinline__ void gemm_body(
    int m0, int n0, const __half* __restrict__ A, const __half* __restrict__ Bp,
    float* __restrict__ C, const int* __restrict__ t2s, const float* __restrict__ sc,
    __half* __restrict__ e0, __half* __restrict__ e1, __half* __restrict__ e2,
    char* smem) {
    constexpr int BM = 128, BK = 64;
    constexpr int THREADS = 128;
    constexpr int STAGE_A = BM * BK * 2;          // 16 KB
    constexpr int STAGE_B = BN * BK * 2;          // 16 or 8 KB
    constexpr int STAGE   = STAGE_A + STAGE_B;
    constexpr int NSTAGE  = 3;
    constexpr int MT   = 4;                       // 16-row m-tiles per warp (64 rows)
    constexpr int WNE  = BN / 2;                  // warp n-extent (64 or 32)
    constexpr int NTL  = WNE / 8;                 // 8-col n-tiles per warp
    constexpr int NPAIR = WNE / 16;               // ldmatrix.x4 loads for B per k-step
    constexpr int ldb    = G1 ? HID : KTOT2;
    constexpr int nctot  = G1 ? 64 : 66;
    constexpr int NCBASE = 64;                    // chunks < 64 come from A (xh)

    const int tid  = threadIdx.x;
    const int wid  = tid >> 5, lane = tid & 31;
    const int wm   = wid & 1, wn = wid >> 1;      // 2 x 2 warp grid
    const uint32_t s_base = smem_u32(smem);

    const __half* AE = nullptr;                   // G2 ext tail source
    if constexpr (!G1) AE = (n0 < QS) ? e0 : (n0 < QS + KVS) ? e1 : e2;

    const int lr   = lane & 7;   // row within 8x8 ldmatrix
    const int lsub = lane >> 3;  // which 8x8 matrix this lane's address feeds
    const int g    = lane >> 2;  // mma group row
    const int t    = lane & 3;   // mma thread-in-group

    bool flag_seen = G1;         // G1 tiles never wait

    auto load_stage = [&](int stage, int c) {
        const uint32_t sa = s_base + stage * STAGE;
        const __half* srcA; size_t ldA;
        if constexpr (G1) {
            srcA = A + (size_t)m0 * HID + (size_t)c * BK; ldA = (size_t)HID;
        } else {
            if (c < NCBASE) {
                srcA = A + (size_t)m0 * HID + (size_t)c * BK; ldA = (size_t)HID;
            } else {
                if (!flag_seen) {
                    while (*((volatile unsigned*)&g_done) < (unsigned)NT1) { }
                    __threadfence();
                    flag_seen = true;
                }
                srcA = AE + (size_t)m0 * SEXT + (size_t)(c - NCBASE) * BK; ldA = SEXT;
            }
        }
        const __half* srcB = Bp + (size_t)n0 * ldb + (size_t)c * BK;
        #pragma unroll
        for (int i = 0; i < BM * 8 / THREADS; i++) {
            int id = tid + i * THREADS; int row = id >> 3, cc = id & 7;
            uint32_t off = (uint32_t)(row * 128 + cc * 16);
            cp_async16(sa + sw128(off), (const char*)srcA + row * ldA * 2 + cc * 16);
        }
        #pragma unroll
        for (int i = 0; i < BN * 8 / THREADS; i++) {
            int id = tid + i * THREADS; int row = id >> 3, cc = id & 7;
            uint32_t off = (uint32_t)(row * 128 + cc * 16);
            cp_async16(sa + STAGE_A + sw128(off), (const char*)srcB + (size_t)row * ldb * 2 + cc * 16);
        }
        CP_COMMIT();
    };

    #pragma unroll
    for (int s = 0; s < NSTAGE; s++) load_stage(s, s);   // prologue: 3 stages in flight

    float acc[MT][NTL][4];
    #pragma unroll
    for (int mi = 0; mi < MT; mi++)
        #pragma unroll
        for (int ni = 0; ni < NTL; ni++)
            #pragma unroll
            for (int q = 0; q < 4; q++) acc[mi][ni][q] = 0.f;

    uint32_t afr[MT][4], bfr[NPAIR][4];

    // fragment loads for k-step ks of the stage at smem offsets (sa, sb)
    auto frag_load = [&](uint32_t sa, uint32_t sb, int ks) {
        #pragma unroll
        for (int mi = 0; mi < MT; mi++) {
            int row  = wm * 64 + mi * 16 + (lsub & 1) * 8 + lr;
            int colh = ks * 16 + (lsub >> 1) * 8;
            uint32_t off = (uint32_t)(row * 128 + colh * 2);
            ldmatrix_x4(afr[mi], sa + sw128(off));
        }
        #pragma unroll
        for (int pi = 0; pi < NPAIR; pi++) {
            int row  = wn * WNE + pi * 16 + (lsub >> 1) * 8 + lr;
            int colh = ks * 16 + (lsub & 1) * 8;
            uint32_t off = (uint32_t)(row * 128 + colh * 2);
            ldmatrix_x4(bfr[pi], sb + sw128(off));
        }
    };

    // wait for chunk 0 (3 groups outstanding -> <=2 leaves chunk 0 complete)
    CP_WAIT(2);
    __syncthreads();
    frag_load(s_base, s_base + STAGE_A, 0);

    int stage_c = 0;
    for (int c = 0; c < nctot; c++) {
        const uint32_t sa = s_base + stage_c * STAGE;
        const uint32_t sb = sa + STAGE_A;
        const int stage_n = (stage_c + 1 == NSTAGE) ? 0 : stage_c + 1;
        const uint32_t sa_n = s_base + stage_n * STAGE;

        #pragma unroll
        for (int ks = 0; ks < 4; ks++) {
            // MMAs consume the fragments loaded for this ks (ks0 was preloaded
            // after the previous iteration's barrier)
            #pragma unroll
            for (int mi = 0; mi < MT; mi++)
                #pragma unroll
                for (int ni = 0; ni < NTL; ni++)
                    mma16816(acc[mi][ni], afr[mi],
                             bfr[ni >> 1][(ni & 1) * 2 + 0],
                             bfr[ni >> 1][(ni & 1) * 2 + 1]);
            if (ks < 3) frag_load(sa, sb, ks + 1);
        }

        // complete chunk c+1 in THIS thread, then barrier: all threads' waits
        // have executed -> chunk c+1 smem writes published, stage (c%3) reads done.
        CP_WAIT(1);
        __syncthreads();
        if (c + 1 < nctot) frag_load(sa_n, sa_n + STAGE_A, 0);  // safe: post-barrier
        if (c + NSTAGE < nctot) load_stage(stage_c, c + NSTAGE);
        else CP_COMMIT();  // keep group count uniform
        stage_c = stage_n;
    }

    if constexpr (G1) {
        // LoRA down-proj epilogue: route + scale + fp16 store into per-target ext
        // bufs. Column j in [0,384) is per-target order (prep permuted lora_A):
        // target = j>>7, rem = j&127 = slot*16 + rank.
        #pragma unroll
        for (int mi = 0; mi < MT; mi++) {
            int r0 = m0 + wm * 64 + mi * 16 + g;
            int slot0 = t2s[r0], slot1 = t2s[r0 + 8];
            float s0 = sc[slot0], s1 = sc[slot1];
            #pragma unroll
            for (int ni = 0; ni < NTL; ni++) {
                int j = n0 + wn * WNE + ni * 8 + 2 * t;
                int it = j >> 7, rem = j & 127;
                int s = rem >> 4;
                __half* ebuf = (it == 0) ? e0 : (it == 1) ? e1 : e2;
                __half2 h0 = (s == slot0)
                    ? __floats2half2_rn(s0 * acc[mi][ni][0], s0 * acc[mi][ni][1])
                    : __floats2half2_rn(0.f, 0.f);
                __half2 h1 = (s == slot1)
                    ? __floats2half2_rn(s1 * acc[mi][ni][2], s1 * acc[mi][ni][3])
                    : __floats2half2_rn(0.f, 0.f);
                *reinterpret_cast<__half2*>(ebuf + (size_t)r0 * SEXT + rem)       = h0;
                *reinterpret_cast<__half2*>(ebuf + (size_t)(r0 + 8) * SEXT + rem) = h1;
            }
        }
        // release: xe visible, then count this tile done
        __threadfence();
        __syncthreads();
        if (tid == 0) atomicAdd(&g_done, 1u);
    } else {
        // fp32 epilogue: streaming stores (write-once output; don't evict the
        // L2-resident W stream that every wave re-reads)
        #pragma unroll
        for (int mi = 0; mi < MT; mi++) {
            int r0 = m0 + wm * 64 + mi * 16 + g;
            #pragma unroll
            for (int ni = 0; ni < NTL; ni++) {
                int col = n0 + wn * WNE + ni * 8 + 2 * t;
                float2 v0 = make_float2(acc[mi][ni][0], acc[mi][ni][1]);
                float2 v1 = make_float2(acc[mi][ni][2], acc[mi][ni][3]);
                __stcs(reinterpret_cast<float2*>(C + (size_t)r0 * NOUT + col), v0);
                __stcs(reinterpret_cast<float2*>(C + (size_t)(r0 + 8) * NOUT + col), v1);
            }
        }
    }
}

// ---------------- fused GEMM1+GEMM2 (single launch) ----------------
// Block order: [0,192) G1 tiles, [192, 3256) full G2 tiles (tiles 0..3063),
// [3256, 3272) thin 128x64 tiles covering the last 8 G2 tiles (m=63, n=40..47).
// First 3256 blocks = exactly 11 full waves at 2 CTAs/SM x 148 SMs; the 16 thin
// tiles (~0.55x duration) pack the final partial wave instead of 8 full tiles
// running ~77us on a 97%-idle chip.
__global__ void __launch_bounds__(128, 2)
hgemm_fused_kernel(const __half* __restrict__ A, const __half* __restrict__ B1,
                   const __half* __restrict__ B2, float* __restrict__ C,
                   const int* __restrict__ t2s, const float* __restrict__ sc,
                   __half* __restrict__ e0, __half* __restrict__ e1,
                   __half* __restrict__ e2) {
    extern __shared__ char smem[];
    const int tau = (int)blockIdx.x;
    if (tau < NT1) {
        int tv = tau;
        gemm_body<true, 128>((tv / 3) * 128, (tv % 3) * 128,
                             A, B1, C, t2s, sc, e0, e1, e2, smem);
    } else if (tau < NT1 + NFULL2) {
        int tv = tau - NT1;
        gemm_body<false, 128>((tv / 48) * 128, (tv % 48) * 128,
                              A, B2, C, t2s, sc, e0, e1, e2, smem);
    } else {
        int idx = tau - NT1 - NFULL2;          // 0..15
        int tv  = NFULL2 + (idx >> 1);         // full-tile index 3064..3071
        int m0  = (tv / 48) * 128;
        int n0  = (tv % 48) * 128 + (idx & 1) * 64;
        gemm_body<false, 64>(m0, n0, A, B2, C, t2s, sc, e0, e1, e2, smem);
    }
}

// ---------------- launch ----------------
extern "C" void kernel_launch(void* const* d_in, const int* in_sizes, int n_in,
                              void* d_out, int out_size) {
    (void)in_sizes; (void)n_in; (void)out_size;
    const float* x   = (const float*)d_in[0];
    const float* W   = (const float*)d_in[1];
    const float* lA  = (const float*)d_in[2];
    const float* bq  = (const float*)d_in[3];
    const float* bk  = (const float*)d_in[4];
    const float* bv  = (const float*)d_in[5];
    const float* sc  = (const float*)d_in[6];
    const int*   t2s = (const int*)d_in[7];
    float* out = (float*)d_out;

    void *xh_p, *wh_p, *ah_p, *xe_p;
    cudaGetSymbolAddress(&xh_p, g_xh);
    cudaGetSymbolAddress(&wh_p, g_wh);
    cudaGetSymbolAddress(&ah_p, g_ah);
    cudaGetSymbolAddress(&xe_p, g_xe);
    __half* xh = (__half*)xh_p;
    __half* wh = (__half*)wh_p;
    __half* ah = (__half*)ah_p;
    __half* xe0 = (__half*)xe_p;
    __half* xe1 = xe0 + (size_t)T_TOK * SEXT;
    __half* xe2 = xe1 + (size_t)T_TOK * SEXT;

    constexpr int SMEM = 3 * (128 * 64 * 2 + 128 * 64 * 2);  // 98304 (2 CTAs/SM)
    cudaFuncSetAttribute((const void*)hgemm_fused_kernel,
                         cudaFuncAttributeMaxDynamicSharedMemorySize, SMEM);

    // 1) full prep: x->fp16, lora_A->fp16 (permuted), W->fp16 + ext fill;
    //    also resets g_done for this replay. (~44us, at the DRAM roofline.)
    {
        int total = T_TOK * 512 + 3 * SEXT * 512 + NOUT * 512 + NOUT * SEXT;
        prep_kernel<<<(total + 255) / 256, 256>>>(x, lA, W, bq, bk, bv, xh, ah, wh);
    }

    // 2) fused GEMM1 + GEMM2 in one launch (thin-tile tail packing):
    //    taus [0,192): a[T,384] = xh @ ah^T with route/scale epilogue -> xe bufs
    //    taus [192,3256): full G2 tiles; taus [3256,3272): thin 128x64 G2 tiles
    {
        int grid = NT1 + NFULL2 + 16;   // 3272
        hgemm_fused_kernel<<<grid, 128, SMEM>>>(
            xh, ah, wh, out, t2s, sc, xe0, xe1, xe2);
    }
}